// round 15
// baseline (speedup 1.0000x reference)
#include <cuda_runtime.h>
#include <math.h>

#define NTOK 8192
#define DDIM 1024
#define NEXP 16
#define GRP  8               // tokens per routing block
#define RBLK (NTOK / GRP)    // 1024 route blocks
#define CBLK (NTOK / 8)      // 1024 combine blocks (8 tokens each, warp/token)
#define FULL 0xffffffffu

typedef unsigned long long u64;

// ---- scratch (device globals: no allocation allowed) ----
__device__ float  g_S[DDIM];          // column sums of h^2 ; zero at load, re-zeroed by moe_loss
__device__ float  g_G[NEXP * NEXP];   // Gram accumulator; zero at load, re-zeroed by moe_loss
__device__ float2 g_route[NTOK];      // per-token (w0, packed(i0,i1)) — overwritten each call

__device__ __forceinline__ void cpasync16(float* dst, const float* src) {
    unsigned d = (unsigned)__cvta_generic_to_shared(dst);
    asm volatile("cp.async.cg.shared.global [%0], [%1], 16;" :: "r"(d), "l"(src));
}
__device__ __forceinline__ void cp_commit() { asm volatile("cp.async.commit_group;"); }
__device__ __forceinline__ void cp_wait0()  { asm volatile("cp.async.wait_group 0;"); }

// ---- packed f32x2 helpers ----
__device__ __forceinline__ u64 fma2(u64 a, u64 b, u64 c) {
    u64 d; asm("fma.rn.f32x2 %0, %1, %2, %3;" : "=l"(d) : "l"(a), "l"(b), "l"(c)); return d;
}
__device__ __forceinline__ u64 mul2(u64 a, u64 b) {
    u64 d; asm("mul.rn.f32x2 %0, %1, %2;" : "=l"(d) : "l"(a), "l"(b)); return d;
}
__device__ __forceinline__ u64 add2(u64 a, u64 b) {
    u64 d; asm("add.rn.f32x2 %0, %1, %2;" : "=l"(d) : "l"(a), "l"(b)); return d;
}
__device__ __forceinline__ u64 pack2(float lo, float hi) {
    u64 d; asm("mov.b64 %0, {%1, %2};" : "=l"(d) : "f"(lo), "f"(hi)); return d;
}
__device__ __forceinline__ void unpack2(u64 v, float& lo, float& hi) {
    asm("mov.b64 {%0, %1}, %2;" : "=f"(lo), "=f"(hi) : "l"(v));
}

// ============================================================================
// K1: ROUTER. 1024 blocks x 256 thr, 8 tokens/block, single smem stage
//   (33 KB -> 3 blocks/SM = 24 warps). Warp = expert-pair; gate streamed
//   from L2 (i-outer); packed math; reduce-scatter; serial top-2 scan.
//   Also accumulates h^2 column sums. Writes (w0, i0|i1) per token.
// ============================================================================
extern "C" __global__ void __launch_bounds__(256, 3)
moe_route(const float* __restrict__ x,
          const float* __restrict__ gate_w,
          const float* __restrict__ gate_b)
{
    __shared__ float h[GRP * DDIM];       // 32 KB
    __shared__ float logit_s[GRP * 17];   // padded

    const int tid  = threadIdx.x;
    const int warp = tid >> 5;
    const int lane = tid & 31;
    const int tok0 = blockIdx.x * GRP;

    // ---- stage 8 tokens ----
    #pragma unroll
    for (int i = 0; i < 8; i++)
        cpasync16(&h[4 * (i * 256 + tid)],
                  x + (size_t)tok0 * DDIM + 4 * (i * 256 + tid));
    cp_commit();

    const ulonglong2* gwp = (const ulonglong2*)(gate_w + 2 * warp * DDIM) + lane;
    const float biasA = __ldg(&gate_b[2 * warp]);
    const float biasB = __ldg(&gate_b[2 * warp + 1]);

    cp_wait0();
    __syncthreads();

    // ---- logits: warp's 2 experts x 8 tokens; gate streamed (i-outer) ----
    u64 aA[8], aB[8];
    #pragma unroll
    for (int t = 0; t < 8; t++) { aA[t] = 0ull; aB[t] = 0ull; }
    #pragma unroll
    for (int i = 0; i < 8; i++) {
        const ulonglong2 g0 = __ldg(gwp + 32 * i);
        const ulonglong2 g1 = __ldg(gwp + 256 + 32 * i);
        #pragma unroll
        for (int t = 0; t < 8; t++) {
            ulonglong2 h2 = *(const ulonglong2*)&h[t * DDIM + 4 * lane + 128 * i];
            aA[t] = fma2(g0.x, h2.x, aA[t]);
            aA[t] = fma2(g0.y, h2.y, aA[t]);
            aB[t] = fma2(g1.x, h2.x, aB[t]);
            aB[t] = fma2(g1.y, h2.y, aB[t]);
        }
    }
    // horizontal add -> acc[16], layout acc[2t + esub]
    float acc[16];
    #pragma unroll
    for (int t = 0; t < 8; t++) {
        float lo, hi;
        unpack2(aA[t], lo, hi); acc[2 * t]     = lo + hi;
        unpack2(aB[t], lo, hi); acc[2 * t + 1] = lo + hi;
    }

    // ---- reduce-scatter 16 accs over 32 lanes (R5-verified pattern) ----
    // final: lane l holds full sum of acc[(l>>1)&15]
    float v8[8];
    #pragma unroll
    for (int j = 0; j < 8; j++) {
        float send = (lane & 16) ? acc[j] : acc[j + 8];
        float recv = __shfl_xor_sync(FULL, send, 16);
        v8[j] = ((lane & 16) ? acc[j + 8] : acc[j]) + recv;
    }
    float v4[4];
    #pragma unroll
    for (int j = 0; j < 4; j++) {
        float send = (lane & 8) ? v8[j] : v8[j + 4];
        float recv = __shfl_xor_sync(FULL, send, 8);
        v4[j] = ((lane & 8) ? v8[j + 4] : v8[j]) + recv;
    }
    float v2[2];
    #pragma unroll
    for (int j = 0; j < 2; j++) {
        float s2 = (lane & 4) ? v4[j] : v4[j + 2];
        float r2 = __shfl_xor_sync(FULL, s2, 4);
        v2[j] = ((lane & 4) ? v4[j + 2] : v4[j]) + r2;
    }
    float s1 = (lane & 2) ? v2[0] : v2[1];
    float r1 = __shfl_xor_sync(FULL, s1, 2);
    float z  = ((lane & 2) ? v2[1] : v2[0]) + r1;
    z += __shfl_xor_sync(FULL, z, 1);

    if (!(lane & 1)) {
        const int j = (lane >> 1) & 15;              // j = 2*t + esub
        const int esub = j & 1;
        logit_s[(j >> 1) * 17 + 2 * warp + esub] = z + (esub ? biasB : biasA);
    }
    __syncthreads();

    // ---- routing: warp 0 scans; lane t (0..7) owns token tok0+t ----
    if (warp == 0) {
        const int t_r = lane & 7;
        float v1 = -1e30f, vv2 = -1e30f; int j1 = 0, j2 = 0;
        #pragma unroll
        for (int e = 0; e < NEXP; e++) {
            float lg = logit_s[t_r * 17 + e];
            if (lg > v1)       { vv2 = v1; j2 = j1; v1 = lg; j1 = e; }
            else if (lg > vv2) { vv2 = lg; j2 = e; }
        }
        if (lane < 8) {
            float w0 = 1.f / (1.f + __expf(vv2 - v1));   // softmax denom cancels
            float2 r;
            r.x = w0;
            r.y = __int_as_float(j1 | (j2 << 8));
            g_route[tok0 + lane] = r;
        }
    }

    // ---- h^2 column partials: thread owns dims [4*tid, 4*tid+4) ----
    {
        u64 p01 = 0ull, p23 = 0ull;
        #pragma unroll
        for (int t = 0; t < 8; t++) {
            ulonglong2 hv = *(const ulonglong2*)&h[t * DDIM + 4 * tid];
            p01 = fma2(hv.x, hv.x, p01);
            p23 = fma2(hv.y, hv.y, p23);
        }
        float a, b, c, d;
        unpack2(p01, a, b);
        unpack2(p23, c, d);
        atomicAdd(&g_S[4 * tid + 0], a);
        atomicAdd(&g_S[4 * tid + 1], b);
        atomicAdd(&g_S[4 * tid + 2], c);
        atomicAdd(&g_S[4 * tid + 3], d);
    }
}

// ============================================================================
// K2: COMBINE. 1024 blocks x 256 thr; warp per token; zero barriers, zero
//   smem. x is L2-resident (router just streamed it); rt_e/sh_e L1-hot.
//   out = h * (sh_sum + w0*r_i0 + w1*r_i1), fully unrolled, MLP ~40.
// ============================================================================
extern "C" __global__ void __launch_bounds__(256)
moe_combine(const float* __restrict__ x,
            const float* __restrict__ sh_e,
            const float* __restrict__ rt_e,
            float* __restrict__ out)
{
    const int warp = threadIdx.x >> 5;
    const int lane = threadIdx.x & 31;
    const int tok  = blockIdx.x * 8 + warp;

    const float2 rt = g_route[tok];
    const float w0 = rt.x;
    const int bits = __float_as_int(rt.y);
    const int i0 = bits & 0xff;
    const int i1 = (bits >> 8) & 0xff;
    const u64 w0p = pack2(w0, w0);
    const u64 w1p = pack2(1.f - w0, 1.f - w0);

    const float* xp  = x    + (size_t)tok * DDIM + 4 * lane;
    float*       op  = out  + (size_t)tok * DDIM + 4 * lane;
    const float* r0p = rt_e + i0 * DDIM + 4 * lane;
    const float* r1p = rt_e + i1 * DDIM + 4 * lane;
    const float* s0p = sh_e + 4 * lane;

    #pragma unroll
    for (int i = 0; i < 8; i++) {
        ulonglong2 h2 = __ldg((const ulonglong2*)(xp  + 128 * i));
        ulonglong2 r0 = __ldg((const ulonglong2*)(r0p + 128 * i));
        ulonglong2 r1 = __ldg((const ulonglong2*)(r1p + 128 * i));
        ulonglong2 sa = __ldg((const ulonglong2*)(s0p + 128 * i));
        ulonglong2 sb = __ldg((const ulonglong2*)(s0p + DDIM + 128 * i));
        u64 shx = add2(sa.x, sb.x);
        u64 shy = add2(sa.y, sb.y);
        ulonglong2 o;
        o.x = mul2(h2.x, fma2(w1p, r1.x, fma2(w0p, r0.x, shx)));
        o.y = mul2(h2.y, fma2(w1p, r1.y, fma2(w0p, r0.y, shy)));
        *(ulonglong2*)(op + 128 * i) = o;
    }
}

// ============================================================================
// K3: d-parallel Gram. 64 blocks own 16-dim slices; thread = (e,f) pair.
// ============================================================================
#define GBLK 64
#define GDIM (DDIM / GBLK)   // 16 dims per block

extern "C" __global__ void __launch_bounds__(256, 4)
moe_gram(const float* __restrict__ rt_e)
{
    __shared__ float rs[NEXP * 17];   // [e][j], padded
    __shared__ float Ss[GDIM];
    const int tid = threadIdx.x;
    const int dbase = blockIdx.x * GDIM;

    {
        const int e = tid >> 4, j = tid & 15;
        rs[e * 17 + j] = __ldg(&rt_e[e * DDIM + dbase + j]);
        if (tid < GDIM) Ss[tid] = g_S[dbase + tid];
    }
    __syncthreads();

    const int e = tid >> 4, f = tid & 15;
    float acc = 0.f;
    #pragma unroll
    for (int j = 0; j < GDIM; j++)
        acc += rs[e * 17 + j] * rs[f * 17 + j] * Ss[j];
    atomicAdd(&g_G[tid], acc);
}

// ============================================================================
// K4: final diversity loss; re-zero g_S and g_G for next graph replay
// ============================================================================
extern "C" __global__ void moe_loss(float* __restrict__ out, int has_loss, int loss_idx)
{
    const int lane = threadIdx.x;   // 32 threads
    const int e = lane & 15;
    float n = sqrtf(g_G[e * NEXP + e]);
    n = fmaxf(n, 1e-8f);
    float s = 0.f;
    #pragma unroll
    for (int f = 0; f < NEXP; f++) {
        float nf = __shfl_sync(FULL, n, f);
        if (f != e) {
            float sim = g_G[e * NEXP + f] / (n * nf);
            sim = fminf(1.f, fmaxf(-1.f, sim));
            s += sim;
        }
    }
    if (lane >= 16) s = 0.f;
    #pragma unroll
    for (int off = 16; off; off >>= 1) s += __shfl_xor_sync(FULL, s, off);
    if (lane == 0 && has_loss)
        out[loss_idx] = s / (float)(NEXP * (NEXP - 1)) * 0.1f;

    // restore invariants for the next iteration (graph replay safe)
    for (int i = lane; i < DDIM; i += 32) g_S[i] = 0.f;
    for (int i = lane; i < NEXP * NEXP; i += 32) g_G[i] = 0.f;
}

// ============================================================================
extern "C" void kernel_launch(void* const* d_in, const int* in_sizes, int n_in,
                              void* d_out, int out_size)
{
    const float* x  = (const float*)d_in[0];
    const float* gw = (const float*)d_in[1];
    const float* gb = (const float*)d_in[2];
    const float* se = (const float*)d_in[3];
    const float* re = (const float*)d_in[4];
    float* out = (float*)d_out;

    moe_route<<<RBLK, 256>>>(x, gw, gb);
    moe_combine<<<CBLK, 256>>>(x, se, re, out);
    moe_gram<<<GBLK, 256>>>(re);

    int has_loss = (out_size > NTOK * DDIM) ? 1 : 0;
    moe_loss<<<1, 32>>>(out, has_loss, out_size - 1);
}

// round 16
// speedup vs baseline: 1.8270x; 1.8270x over previous
#include <cuda_runtime.h>
#include <math.h>

#define NTOK 8192
#define DDIM 1024
#define NEXP 16
#define GRP  8               // tokens per group
#define NGRPS 4              // groups per block
#define TPB  (GRP * NGRPS)   // 32 tokens per block
#define NBLK (NTOK / TPB)    // 256 blocks
#define FULL 0xffffffffu
#define HBUF (GRP * DDIM)    // floats per h buffer

typedef unsigned long long u64;

// ---- scratch (device globals: no allocation allowed) ----
__device__ float g_S[DDIM];          // column sums of h^2 ; zero at load, re-zeroed by moe_loss
__device__ float g_G[NEXP * NEXP];   // Gram accumulator; zero at load, re-zeroed by moe_loss

__device__ __forceinline__ void cpasync16(float* dst, const float* src) {
    unsigned d = (unsigned)__cvta_generic_to_shared(dst);
    asm volatile("cp.async.cg.shared.global [%0], [%1], 16;" :: "r"(d), "l"(src));
}
__device__ __forceinline__ void cp_commit() { asm volatile("cp.async.commit_group;"); }
__device__ __forceinline__ void cp_wait1()  { asm volatile("cp.async.wait_group 1;"); }

// ---- packed f32x2 helpers (PTX-only; ptxas won't auto-fuse) ----
__device__ __forceinline__ u64 fma2(u64 a, u64 b, u64 c) {
    u64 d; asm("fma.rn.f32x2 %0, %1, %2, %3;" : "=l"(d) : "l"(a), "l"(b), "l"(c)); return d;
}
__device__ __forceinline__ u64 mul2(u64 a, u64 b) {
    u64 d; asm("mul.rn.f32x2 %0, %1, %2;" : "=l"(d) : "l"(a), "l"(b)); return d;
}
__device__ __forceinline__ u64 add2(u64 a, u64 b) {
    u64 d; asm("add.rn.f32x2 %0, %1, %2;" : "=l"(d) : "l"(a), "l"(b)); return d;
}
__device__ __forceinline__ u64 pack2(float lo, float hi) {
    u64 d; asm("mov.b64 %0, {%1, %2};" : "=l"(d) : "f"(lo), "f"(hi)); return d;
}
__device__ __forceinline__ void unpack2(u64 v, float& lo, float& hi) {
    asm("mov.b64 {%0, %1}, %2;" : "=f"(lo), "=f"(hi) : "l"(v));
}

// ============================================================================
// K1 (R10 verbatim, 33.2us best measured): fused router + combine, packed
//   f32x2. Triple-buffered cp.async h staging (96 KB dyn), 2 blocks/SM,
//   gate register-resident (packed), serial-scan router, packed combine.
// ============================================================================
extern "C" __global__ void __launch_bounds__(256, 2)
moe_main(const float* __restrict__ x,
         const float* __restrict__ gate_w,
         const float* __restrict__ gate_b,
         const float* __restrict__ sh_e,
         const float* __restrict__ rt_e,
         float* __restrict__ out)
{
    extern __shared__ float h_s[];         // 3 * 32 KB
    __shared__ float logit_s[GRP * 17];    // padded stride 17 (bias folded in)

    const int tid  = threadIdx.x;
    const int warp = tid >> 5;
    const int lane = tid & 31;
    const int tok0 = blockIdx.x * TPB;

    // ---- prefetch groups 0 and 1 ----
    #pragma unroll
    for (int i = 0; i < 8; i++)
        cpasync16(&h_s[0 * HBUF + 4 * (i * 256 + tid)],
                  x + (size_t)tok0 * DDIM + 4 * (i * 256 + tid));
    cp_commit();
    #pragma unroll
    for (int i = 0; i < 8; i++)
        cpasync16(&h_s[1 * HBUF + 4 * (i * 256 + tid)],
                  x + (size_t)(tok0 + GRP) * DDIM + 4 * (i * 256 + tid));
    cp_commit();

    // ---- gate rows 2*warp, 2*warp+1 as packed pairs ----
    ulonglong2 gA2[8], gB2[8];
    {
        const ulonglong2* gwp = (const ulonglong2*)(gate_w + 2 * warp * DDIM) + lane;
        #pragma unroll
        for (int i = 0; i < 8; i++) {
            gA2[i] = gwp[32 * i];
            gB2[i] = gwp[256 + 32 * i];
        }
    }
    const float biasA = __ldg(&gate_b[2 * warp]);
    const float biasB = __ldg(&gate_b[2 * warp + 1]);

    // ---- combine dim-slice + shared-expert sum (packed) ----
    const int d0 = 128 * warp + 4 * lane;
    u64 sh01, sh23;
    {
        ulonglong2 a = *(const ulonglong2*)(sh_e + d0);
        ulonglong2 b = *(const ulonglong2*)(sh_e + DDIM + d0);
        sh01 = add2(a.x, b.x);
        sh23 = add2(a.y, b.y);
    }
    u64 s2a = 0ull, s2b = 0ull;            // packed h^2 partials

    #pragma unroll
    for (int grp = 0; grp < NGRPS; grp++) {
        const int tbase = tok0 + grp * GRP;
        const float* hbuf = h_s + (grp % 3) * HBUF;

        cp_wait1();          // group `grp` landed
        __syncthreads();     // visible to all; all warps past group grp-1 combine

        // ---- early prefetch grp+2 into buffer (grp+2)%3 ----
        if (grp + 2 < NGRPS) {
            const float* src = x + (size_t)(tok0 + (grp + 2) * GRP) * DDIM;
            float* dst = h_s + ((grp + 2) % 3) * HBUF;
            #pragma unroll
            for (int i = 0; i < 8; i++)
                cpasync16(&dst[4 * (i * 256 + tid)], src + 4 * (i * 256 + tid));
        }
        cp_commit();         // commit every group to keep wait-counts aligned

        // ---- logits: 2 experts x 8 tokens, packed f32x2, two 4-token passes ----
        #pragma unroll
        for (int p = 0; p < 2; p++) {
            u64 aA[4], aB[4];
            #pragma unroll
            for (int t = 0; t < 4; t++) { aA[t] = 0ull; aB[t] = 0ull; }
            #pragma unroll
            for (int i = 0; i < 8; i++) {
                const u64 ga01 = gA2[i].x, ga23 = gA2[i].y;
                const u64 gb01 = gB2[i].x, gb23 = gB2[i].y;
                #pragma unroll
                for (int t = 0; t < 4; t++) {
                    ulonglong2 h2 = *(const ulonglong2*)
                        &hbuf[(4 * p + t) * DDIM + 4 * lane + 128 * i];
                    aA[t] = fma2(ga01, h2.x, aA[t]);
                    aA[t] = fma2(ga23, h2.y, aA[t]);
                    aB[t] = fma2(gb01, h2.x, aB[t]);
                    aB[t] = fma2(gb23, h2.y, aB[t]);
                }
            }
            // horizontal add of packed halves -> 8 scalars (j = 2*t + esub)
            float acc[8];
            #pragma unroll
            for (int t = 0; t < 4; t++) {
                float lo, hi;
                unpack2(aA[t], lo, hi); acc[2 * t]     = lo + hi;
                unpack2(aB[t], lo, hi); acc[2 * t + 1] = lo + hi;
            }
            // reduce-scatter 8 values over 32 lanes;
            // final: lanes with (lane&3)==0 hold j = 4*b4 + 2*b3 + b2
            float v4[4];
            #pragma unroll
            for (int j = 0; j < 4; j++) {
                float send = (lane & 16) ? acc[j] : acc[j + 4];
                float recv = __shfl_xor_sync(FULL, send, 16);
                v4[j] = ((lane & 16) ? acc[j + 4] : acc[j]) + recv;
            }
            float v2[2];
            #pragma unroll
            for (int j = 0; j < 2; j++) {
                float s2 = (lane & 8) ? v4[j] : v4[j + 2];
                float r2 = __shfl_xor_sync(FULL, s2, 8);
                v2[j] = ((lane & 8) ? v4[j + 2] : v4[j]) + r2;
            }
            float s1 = (lane & 4) ? v2[0] : v2[1];
            float r1 = __shfl_xor_sync(FULL, s1, 4);
            float z  = ((lane & 4) ? v2[1] : v2[0]) + r1;
            z += __shfl_xor_sync(FULL, z, 2);
            z += __shfl_xor_sync(FULL, z, 1);

            if ((lane & 3) == 0) {
                const int j = 4 * ((lane >> 4) & 1) + 2 * ((lane >> 3) & 1) + ((lane >> 2) & 1);
                const int esub = j & 1;
                logit_s[(4 * p + (j >> 1)) * 17 + 2 * warp + esub]
                    = z + (esub ? biasB : biasA);
            }
        }
        __syncthreads();

        // ---- router: serial top-2 scan; lane routes token (lane & 7) ----
        const int t_r = lane & 7;
        float v1 = -1e30f, vv2 = -1e30f; int j1 = 0, j2 = 0;
        #pragma unroll
        for (int e = 0; e < NEXP; e++) {
            float lg = logit_s[t_r * 17 + e];
            if (lg > v1)       { vv2 = v1; j2 = j1; v1 = lg; j1 = e; }
            else if (lg > vv2) { vv2 = lg; j2 = e; }
        }
        const float w0s = 1.f / (1.f + __expf(vv2 - v1));   // softmax denom cancels
        const int i0s = j1, i1s = j2;

        // ---- combine (dim-sliced, packed): warp covers dims [128w, 128w+128) ----
        #pragma unroll
        for (int t = 0; t < 8; t++) {
            const float w0 = __shfl_sync(FULL, w0s, t);
            const int   i0 = __shfl_sync(FULL, i0s, t);
            const int   i1 = __shfl_sync(FULL, i1s, t);
            const u64 w0p = pack2(w0, w0);
            const u64 w1p = pack2(1.f - w0, 1.f - w0);
            ulonglong2 h2 = *(const ulonglong2*)&hbuf[t * DDIM + d0];
            ulonglong2 r0 = *(const ulonglong2*)(rt_e + i0 * DDIM + d0);
            ulonglong2 r1 = *(const ulonglong2*)(rt_e + i1 * DDIM + d0);
            ulonglong2 o;
            o.x = mul2(h2.x, fma2(w1p, r1.x, fma2(w0p, r0.x, sh01)));
            o.y = mul2(h2.y, fma2(w1p, r1.y, fma2(w0p, r0.y, sh23)));
            *(ulonglong2*)(out + (size_t)(tbase + t) * DDIM + d0) = o;
            s2a = fma2(h2.x, h2.x, s2a);
            s2b = fma2(h2.y, h2.y, s2b);
        }
        // no end-of-group barrier: next group's first barrier protects buffers
    }

    {
        float sx, sy, sz, sw;
        unpack2(s2a, sx, sy);
        unpack2(s2b, sz, sw);
        atomicAdd(&g_S[d0 + 0], sx);
        atomicAdd(&g_S[d0 + 1], sy);
        atomicAdd(&g_S[d0 + 2], sz);
        atomicAdd(&g_S[d0 + 3], sw);
    }
}

// ============================================================================
// K2: d-parallel Gram. 64 blocks own 16-dim slices; thread = (e,f) pair;
//   smem-staged rt slice (pad 17) + S slice; one atomicAdd into g_G.
// ============================================================================
#define GBLK 64
#define GDIM (DDIM / GBLK)   // 16 dims per block

extern "C" __global__ void __launch_bounds__(256, 4)
moe_gram(const float* __restrict__ rt_e)
{
    __shared__ float rs[NEXP * 17];   // [e][j], padded
    __shared__ float Ss[GDIM];
    const int tid = threadIdx.x;
    const int dbase = blockIdx.x * GDIM;

    {
        const int e = tid >> 4, j = tid & 15;
        rs[e * 17 + j] = __ldg(&rt_e[e * DDIM + dbase + j]);
        if (tid < GDIM) Ss[tid] = g_S[dbase + tid];
    }
    __syncthreads();

    const int e = tid >> 4, f = tid & 15;
    float acc = 0.f;
    #pragma unroll
    for (int j = 0; j < GDIM; j++)
        acc += rs[e * 17 + j] * rs[f * 17 + j] * Ss[j];
    atomicAdd(&g_G[tid], acc);
}

// ============================================================================
// K3: final diversity loss (g_G row preloaded with independent loads — fixes
//   the serialized-load chain seen in R15's profile); re-zero g_S/g_G with
//   256 threads for next graph replay.
// ============================================================================
extern "C" __global__ void __launch_bounds__(256)
moe_loss(float* __restrict__ out, int has_loss, int loss_idx)
{
    const int tid = threadIdx.x;

    if (tid < 32) {
        const int lane = tid;
        const int e = lane & 15;
        // preload whole row: 16 independent loads, MLP=16 (one latency exposure)
        float gv[NEXP];
        #pragma unroll
        for (int f = 0; f < NEXP; f++) gv[f] = __ldg(&g_G[e * NEXP + f]);

        float n = sqrtf(gv[e]);
        n = fmaxf(n, 1e-8f);
        float s = 0.f;
        #pragma unroll
        for (int f = 0; f < NEXP; f++) {
            float nf = __shfl_sync(FULL, n, f);
            if (f != e) {
                float sim = gv[f] / (n * nf);
                sim = fminf(1.f, fmaxf(-1.f, sim));
                s += sim;
            }
        }
        if (lane >= 16) s = 0.f;
        #pragma unroll
        for (int off = 16; off; off >>= 1) s += __shfl_xor_sync(FULL, s, off);
        if (lane == 0 && has_loss)
            out[loss_idx] = s / (float)(NEXP * (NEXP - 1)) * 0.1f;
    }

    // restore invariants for the next iteration (graph replay safe).
    // Safe to overlap with warp 0's loss math: loss reads only g_G values
    // already preloaded into registers... but g_G zeroing must still wait.
    __syncthreads();
    for (int i = tid; i < DDIM; i += 256) g_S[i] = 0.f;
    if (tid < NEXP * NEXP) g_G[tid] = 0.f;
}

// ============================================================================
extern "C" void kernel_launch(void* const* d_in, const int* in_sizes, int n_in,
                              void* d_out, int out_size)
{
    const float* x  = (const float*)d_in[0];
    const float* gw = (const float*)d_in[1];
    const float* gb = (const float*)d_in[2];
    const float* se = (const float*)d_in[3];
    const float* re = (const float*)d_in[4];
    float* out = (float*)d_out;

    const int SMEM1 = 3 * HBUF * (int)sizeof(float);   // 96 KB dynamic
    cudaFuncSetAttribute((const void*)moe_main,
                         cudaFuncAttributeMaxDynamicSharedMemorySize, SMEM1);

    moe_main<<<NBLK, 256, SMEM1>>>(x, gw, gb, se, re, out);
    moe_gram<<<GBLK, 256>>>(re);

    int has_loss = (out_size > NTOK * DDIM) ? 1 : 0;
    moe_loss<<<1, 256>>>(out, has_loss, out_size - 1);
}